// round 10
// baseline (speedup 1.0000x reference)
#include <cuda_runtime.h>
#include <cuda_fp16.h>
#include <cstdint>
#include <cstddef>

#define H 128
#define NCUST_MAX 1000000
#define NART_MAX  100000

// U = Zc @ W1c, V = Za @ W1a + b1, stored fp16
__device__ __half g_U[(size_t)NCUST_MAX * H];
__device__ __half g_V[(size_t)NART_MAX * H];
__device__ int    g_idx64;   // 1 if row/col are int64, 0 if int32

__device__ __forceinline__ uint32_t smem_u32(const void* p) {
    uint32_t a;
    asm("{ .reg .u64 t; cvta.to.shared.u64 t, %1; cvt.u32.u64 %0, t; }" : "=r"(a) : "l"(p));
    return a;
}

__device__ __forceinline__ void mma_f16(float c[4],
                                        uint32_t a0, uint32_t a1, uint32_t a2, uint32_t a3,
                                        uint32_t b0, uint32_t b1) {
    asm volatile(
        "mma.sync.aligned.m16n8k16.row.col.f32.f16.f16.f32 "
        "{%0,%1,%2,%3}, {%4,%5,%6,%7}, {%8,%9}, {%0,%1,%2,%3};"
        : "+f"(c[0]), "+f"(c[1]), "+f"(c[2]), "+f"(c[3])
        : "r"(a0), "r"(a1), "r"(a2), "r"(a3), "r"(b0), "r"(b1));
}

__device__ __forceinline__ uint32_t pack_h2(float lo, float hi) {
    __half2 h = __floats2half2_rn(lo, hi);
    return *(uint32_t*)&h;
}

__device__ __forceinline__ void cp16(uint32_t dst, const void* src) {
    asm volatile("cp.async.ca.shared.global [%0], [%1], 16;" :: "r"(dst), "l"(src));
}
#define CP_COMMIT() asm volatile("cp.async.commit_group;" ::: "memory")
#define CP_WAIT1()  asm volatile("cp.async.wait_group 1;" ::: "memory")

// ---- probe: int64 vs int32 indices -------------------------------------
__global__ void probe_idx_dtype(const int* __restrict__ idx32, int n_elems) {
    int all_zero = 1;
#pragma unroll
    for (int i = 0; i < 16; i++) {
        int pos = 2 * i + 1;
        if (pos < 2 * n_elems && idx32[pos] != 0) all_zero = 0;
    }
    g_idx64 = all_zero;
}

// ---- persistent fp16 GEMM: C[M,128] = half(A[M,128] @ B[128,128] (+bias))
// 128 threads (4 warps), M-tile = 64, 2 CTAs/SM (98KB smem each).
// SMEM: Bf = m16n8k16 B fragments (8kt x 16nt x 32 lanes x uint2, 32KB),
//       As[2] = double-buffered A tiles, 64 x 132 fp32 raw.
#define AS_STRIDE 132
#define BF_BYTES  32768
#define AS_BYTES  (64 * AS_STRIDE * 4)
#define SMEM_TOT  (BF_BYTES + 2 * AS_BYTES)

__global__ void __launch_bounds__(128) gemm_tc(const float* __restrict__ A,
                                               const float* __restrict__ B,
                                               __half* __restrict__ C,
                                               const float* __restrict__ bias,
                                               int M, int nTiles) {
    extern __shared__ char smem[];
    uint2* Bf = (uint2*)smem;
    float* As0 = (float*)(smem + BF_BYTES);
    float* As1 = (float*)(smem + BF_BYTES + AS_BYTES);
    const uint32_t asAddr0 = smem_u32(As0);
    const uint32_t asAddr1 = smem_u32(As1);

    const int tid  = threadIdx.x;
    const int wid  = tid >> 5;
    const int lane = tid & 31;
    const int qrow = lane >> 2;   // 0..7
    const int qk   = lane & 3;    // 0..3
    const int mBase = wid * 16;

    // One-time: pack B into exact m16n8k16 per-lane fragments.
    for (int idx = tid; idx < 8 * 16 * 32; idx += 128) {
        int kt = idx >> 9;
        int nt = (idx >> 5) & 15;
        int l  = idx & 31;
        int k0 = kt * 16 + (l & 3) * 2;
        int n  = nt * 8 + (l >> 2);
        uint2 v;
        v.x = pack_h2(B[k0 * H + n],       B[(k0 + 1) * H + n]);
        v.y = pack_h2(B[(k0 + 8) * H + n], B[(k0 + 9) * H + n]);
        Bf[idx] = v;
    }

    const long long t0 = blockIdx.x;
    const long long s  = gridDim.x;

    // Async A-tile stage: 64 rows x 512B = 2048 x 16B chunks.
    auto issue = [&](long long tile, uint32_t dstBase) {
        if (tile < (long long)nTiles) {
            long long r0 = tile * 64;
#pragma unroll 4
            for (int c = tid; c < 2048; c += 128) {
                int r = c >> 5, q = c & 31;
                long long gr = r0 + r;
                if (gr >= (long long)M) gr = (long long)M - 1;  // clamp; store guarded
                cp16(dstBase + (uint32_t)(r * (AS_STRIDE * 4) + q * 16),
                     A + gr * (long long)H + q * 4);
            }
        }
        CP_COMMIT();
    };

    issue(t0, asAddr0);
    issue(t0 + s, asAddr1);

    int b = 0;
    for (long long t = t0; t < (long long)nTiles; t += s, b ^= 1) {
        CP_WAIT1();
        __syncthreads();   // also covers Bf staging on first iteration

        const float* as = b ? As1 : As0;
        float acc[16][4];
#pragma unroll
        for (int nt = 0; nt < 16; nt++) {
            acc[nt][0] = 0.f; acc[nt][1] = 0.f; acc[nt][2] = 0.f; acc[nt][3] = 0.f;
        }

#pragma unroll
        for (int kt = 0; kt < 8; kt++) {
            const int k0 = kt * 16 + qk * 2;
            const float* ar0 = as + (mBase + qrow) * AS_STRIDE;
            const float* ar1 = as + (mBase + qrow + 8) * AS_STRIDE;
            float2 lo0 = *(const float2*)(ar0 + k0);
            float2 lo1 = *(const float2*)(ar1 + k0);
            float2 hi0 = *(const float2*)(ar0 + k0 + 8);
            float2 hi1 = *(const float2*)(ar1 + k0 + 8);
            uint32_t a0 = pack_h2(lo0.x, lo0.y);
            uint32_t a1 = pack_h2(lo1.x, lo1.y);
            uint32_t a2 = pack_h2(hi0.x, hi0.y);
            uint32_t a3 = pack_h2(hi1.x, hi1.y);
            const uint2* bf = Bf + (kt * 16) * 32 + lane;
#pragma unroll
            for (int nt = 0; nt < 16; nt++) {
                uint2 bv = bf[nt * 32];
                mma_f16(acc[nt], a0, a1, a2, a3, bv.x, bv.y);
            }
        }

        // Epilogue: fp16 store (+bias for V).
        const long long row0 = t * 64;
        const long long gr0 = row0 + mBase + qrow;
        const long long gr1 = gr0 + 8;
        const int nc = qk * 2;
        const bool w0 = gr0 < (long long)M;
        const bool w1 = gr1 < (long long)M;
#pragma unroll
        for (int nt = 0; nt < 16; nt++) {
            const int c0 = nt * 8 + nc;
            float bz0 = 0.f, bz1 = 0.f;
            if (bias) { bz0 = __ldg(bias + c0); bz1 = __ldg(bias + c0 + 1); }
            if (w0) {
                __half2 h = __floats2half2_rn(acc[nt][0] + bz0, acc[nt][1] + bz1);
                *(__half2*)(C + gr0 * H + c0) = h;
            }
            if (w1) {
                __half2 h = __floats2half2_rn(acc[nt][2] + bz0, acc[nt][3] + bz1);
                *(__half2*)(C + gr1 * H + c0) = h;
            }
        }

        __syncthreads();
        issue(t + 2 * s, b ? asAddr1 : asAddr0);
    }
}

// ---- edge pass ----------------------------------------------------------
// out[e] = b2 + sum_j relu(U[row[e]][j] + V[col[e]][j]) * W2[j]   (b1 in V)
// 8 lanes per edge, 4 edges per warp per iter.
// lane = (c<<2)|j : j = edge slot (0-3), c = 16-channel block (0-7).
// Loads: 2x LDG.128 per lane per array -> fully coalesced 128B bursts.
__global__ void __launch_bounds__(256) edge_k(const __half* __restrict__ U,
                                              const __half* __restrict__ V,
                                              const void* __restrict__ rowp,
                                              const void* __restrict__ colp,
                                              const float* __restrict__ W2,
                                              const float* __restrict__ b2,
                                              float* __restrict__ out,
                                              int E) {
    const int lane = threadIdx.x & 31;
    const int j = lane & 3;        // edge slot
    const int c = lane >> 2;       // channel block (16 ch)
    const int w  = (blockIdx.x * blockDim.x + threadIdx.x) >> 5;
    const int nW = (gridDim.x * blockDim.x) >> 5;

    const bool idx64 = (g_idx64 != 0);
    const int*       r32 = (const int*)rowp;
    const int*       c32 = (const int*)colp;
    const long long* r64 = (const long long*)rowp;
    const long long* c64 = (const long long*)colp;

    // W2 channels c*16 .. c*16+15 (fp32, hoisted)
    const float4 w2a = ((const float4*)W2)[c * 4 + 0];
    const float4 w2b = ((const float4*)W2)[c * 4 + 1];
    const float4 w2c = ((const float4*)W2)[c * 4 + 2];
    const float4 w2d = ((const float4*)W2)[c * 4 + 3];
    const float bias2 = b2[0];
    const __half2 zero = __float2half2_rn(0.f);

    for (int e = 4 * w; e < E; e += 4 * nW) {
        int ej = e + j;
        if (ej >= E) ej = E - 1;          // clamp; store guarded
        long long r, ci;
        if (idx64) { r = r64[ej]; ci = c64[ej]; }
        else       { r = (long long)r32[ej]; ci = (long long)c32[ej]; }

        const uint4* up = (const uint4*)(U + r  * (long long)H) + c * 2;
        const uint4* vp = (const uint4*)(V + ci * (long long)H) + c * 2;
        uint4 u0 = up[0], u1 = up[1];
        uint4 v0 = vp[0], v1 = vp[1];

        float s = 0.f;
        {
            const __half2* uh = (const __half2*)&u0;
            const __half2* vh = (const __half2*)&v0;
            float2 f0 = __half22float2(__hmax2(__hadd2(uh[0], vh[0]), zero));
            float2 f1 = __half22float2(__hmax2(__hadd2(uh[1], vh[1]), zero));
            float2 f2 = __half22float2(__hmax2(__hadd2(uh[2], vh[2]), zero));
            float2 f3 = __half22float2(__hmax2(__hadd2(uh[3], vh[3]), zero));
            s = fmaf(f0.x, w2a.x, s); s = fmaf(f0.y, w2a.y, s);
            s = fmaf(f1.x, w2a.z, s); s = fmaf(f1.y, w2a.w, s);
            s = fmaf(f2.x, w2b.x, s); s = fmaf(f2.y, w2b.y, s);
            s = fmaf(f3.x, w2b.z, s); s = fmaf(f3.y, w2b.w, s);
        }
        {
            const __half2* uh = (const __half2*)&u1;
            const __half2* vh = (const __half2*)&v1;
            float2 f0 = __half22float2(__hmax2(__hadd2(uh[0], vh[0]), zero));
            float2 f1 = __half22float2(__hmax2(__hadd2(uh[1], vh[1]), zero));
            float2 f2 = __half22float2(__hmax2(__hadd2(uh[2], vh[2]), zero));
            float2 f3 = __half22float2(__hmax2(__hadd2(uh[3], vh[3]), zero));
            s = fmaf(f0.x, w2c.x, s); s = fmaf(f0.y, w2c.y, s);
            s = fmaf(f1.x, w2c.z, s); s = fmaf(f1.y, w2c.w, s);
            s = fmaf(f2.x, w2d.x, s); s = fmaf(f2.y, w2d.y, s);
            s = fmaf(f3.x, w2d.z, s); s = fmaf(f3.y, w2d.w, s);
        }

        // Reduce over the 8 lanes sharing j (lanes differ in bits 2..4).
        s += __shfl_xor_sync(0xffffffffu, s, 16);
        s += __shfl_xor_sync(0xffffffffu, s, 8);
        s += __shfl_xor_sync(0xffffffffu, s, 4);

        if (c == 0 && e + j < E) out[e + j] = s + bias2;
    }
}

extern "C" void kernel_launch(void* const* d_in, const int* in_sizes, int n_in,
                              void* d_out, int out_size) {
    const float* zc  = (const float*)d_in[0];
    const float* za  = (const float*)d_in[1];
    const void*  row = d_in[2];
    const void*  col = d_in[3];
    const float* W1  = (const float*)d_in[4];
    const float* b1  = (const float*)d_in[5];
    const float* W2  = (const float*)d_in[6];
    const float* b2  = (const float*)d_in[7];
    float* out = (float*)d_out;

    const int Mc = in_sizes[0] / H;
    const int Ma = in_sizes[1] / H;
    const int E  = in_sizes[2];
    const int nTc = (Mc + 63) / 64;
    const int nTa = (Ma + 63) / 64;

    __half* U = nullptr;
    __half* V = nullptr;
    cudaGetSymbolAddress((void**)&U, g_U);
    cudaGetSymbolAddress((void**)&V, g_V);

    int nSM = 148;
    cudaDeviceGetAttribute(&nSM, cudaDevAttrMultiProcessorCount, 0);

    cudaFuncSetAttribute(gemm_tc, cudaFuncAttributeMaxDynamicSharedMemorySize, SMEM_TOT);

    probe_idx_dtype<<<1, 1>>>((const int*)row, E);
    gemm_tc<<<2 * nSM, 128, SMEM_TOT>>>(zc, W1, U, nullptr, Mc, nTc);
    gemm_tc<<<2 * nSM, 128, SMEM_TOT>>>(za, W1 + H * H, V, b1, Ma, nTa);
    edge_k<<<4096, 256>>>(U, V, row, col, W2, b2, out, E);
}

// round 11
// speedup vs baseline: 1.1056x; 1.1056x over previous
#include <cuda_runtime.h>
#include <cuda_fp16.h>
#include <cstdint>
#include <cstddef>

#define H 128
#define NCUST_MAX 1000000
#define NART_MAX  100000

// U = Zc @ W1c, V = Za @ W1a + b1, stored fp16
__device__ __half g_U[(size_t)NCUST_MAX * H];
__device__ __half g_V[(size_t)NART_MAX * H];
__device__ int    g_idx64;   // 1 if row/col are int64, 0 if int32

__device__ __forceinline__ void mma_f16(float c[4],
                                        uint32_t a0, uint32_t a1, uint32_t a2, uint32_t a3,
                                        uint32_t b0, uint32_t b1) {
    asm volatile(
        "mma.sync.aligned.m16n8k16.row.col.f32.f16.f16.f32 "
        "{%0,%1,%2,%3}, {%4,%5,%6,%7}, {%8,%9}, {%0,%1,%2,%3};"
        : "+f"(c[0]), "+f"(c[1]), "+f"(c[2]), "+f"(c[3])
        : "r"(a0), "r"(a1), "r"(a2), "r"(a3), "r"(b0), "r"(b1));
}

__device__ __forceinline__ uint32_t pack_h2(float lo, float hi) {
    __half2 h = __floats2half2_rn(lo, hi);
    return *(uint32_t*)&h;
}

// ---- probe: int64 vs int32 indices -------------------------------------
__global__ void probe_idx_dtype(const int* __restrict__ idx32, int n_elems) {
    int all_zero = 1;
#pragma unroll
    for (int i = 0; i < 16; i++) {
        int pos = 2 * i + 1;
        if (pos < 2 * n_elems && idx32[pos] != 0) all_zero = 0;
    }
    g_idx64 = all_zero;
}

// ---- persistent fp16 GEMM: C[M,128] = half(A[M,128] @ B[128,128] (+bias))
// 256 threads (8 warps), M-tile 128, persistent grid = #SMs.
// A fragments are warp-private -> loaded DIRECTLY from global into registers
// (no smem staging, no per-tile syncs), register double-buffered.
// B pre-packed once into smem as exact m16n8k16 per-lane fragments (32KB).
__global__ void __launch_bounds__(256) gemm_tc(const float* __restrict__ A,
                                               const float* __restrict__ B,
                                               __half* __restrict__ C,
                                               const float* __restrict__ bias,
                                               int M, int nTiles) {
    __shared__ uint2 Bf[8 * 16 * 32];

    const int tid  = threadIdx.x;
    const int wid  = tid >> 5;
    const int lane = tid & 31;
    const int qrow = lane >> 2;   // 0..7
    const int qk   = lane & 3;    // 0..3
    const int mBase = wid * 16;

    // One-time: pack B (rn-to-fp16) into m16n8k16 per-lane fragments.
    // (kt, nt, l): b0 = {B[k0][n], B[k0+1][n]}, b1 = {B[k0+8][n], B[k0+9][n]},
    //   k0 = kt*16 + (l&3)*2, n = nt*8 + (l>>2).
    for (int idx = tid; idx < 8 * 16 * 32; idx += 256) {
        int kt = idx >> 9;
        int nt = (idx >> 5) & 15;
        int l  = idx & 31;
        int k0 = kt * 16 + (l & 3) * 2;
        int n  = nt * 8 + (l >> 2);
        uint2 v;
        v.x = pack_h2(B[k0 * H + n],       B[(k0 + 1) * H + n]);
        v.y = pack_h2(B[(k0 + 8) * H + n], B[(k0 + 9) * H + n]);
        Bf[idx] = v;
    }
    __syncthreads();

    const long long s = gridDim.x;

    // Raw A fragment buffer for one tile (this lane's exact mma elements):
    // rows r0 = tile*128 + mBase + qrow, r1 = r0 + 8;
    // per kt: float2 at k0 = kt*16 + 2*qk and at k0 + 8, for both rows.
    float2 rl0[8], rl1[8], rh0[8], rh1[8];

    auto loadRaw = [&](long long tile) {
        if (tile >= (long long)nTiles) return;  // stale regs unused
        long long g0 = tile * 128 + mBase + qrow;
        long long g1 = g0 + 8;
        if (g0 >= (long long)M) g0 = (long long)M - 1;  // clamp; store guarded
        if (g1 >= (long long)M) g1 = (long long)M - 1;
        const float* p0 = A + g0 * (long long)H;
        const float* p1 = A + g1 * (long long)H;
#pragma unroll
        for (int kt = 0; kt < 8; kt++) {
            const int k0 = kt * 16 + qk * 2;
            rl0[kt] = *(const float2*)(p0 + k0);
            rl1[kt] = *(const float2*)(p1 + k0);
            rh0[kt] = *(const float2*)(p0 + k0 + 8);
            rh1[kt] = *(const float2*)(p1 + k0 + 8);
        }
    };

    long long t = blockIdx.x;
    loadRaw(t);

    for (; t < (long long)nTiles; t += s) {
        // Convert raw -> packed half2 fragments (frees raw for the prefetch).
        uint32_t pa0[8], pa1[8], pa2[8], pa3[8];
#pragma unroll
        for (int kt = 0; kt < 8; kt++) {
            pa0[kt] = pack_h2(rl0[kt].x, rl0[kt].y);
            pa1[kt] = pack_h2(rl1[kt].x, rl1[kt].y);
            pa2[kt] = pack_h2(rh0[kt].x, rh0[kt].y);
            pa3[kt] = pack_h2(rh1[kt].x, rh1[kt].y);
        }
        // Prefetch next tile while this tile's MMAs run.
        loadRaw(t + s);

        float acc[16][4];
#pragma unroll
        for (int nt = 0; nt < 16; nt++) {
            acc[nt][0] = 0.f; acc[nt][1] = 0.f; acc[nt][2] = 0.f; acc[nt][3] = 0.f;
        }

#pragma unroll
        for (int kt = 0; kt < 8; kt++) {
            const uint2* bf = Bf + (kt * 16) * 32 + lane;
#pragma unroll
            for (int nt = 0; nt < 16; nt++) {
                uint2 bv = bf[nt * 32];
                mma_f16(acc[nt], pa0[kt], pa1[kt], pa2[kt], pa3[kt], bv.x, bv.y);
            }
        }

        // Epilogue: fp16 store (+bias for V).
        const long long row0 = t * 128;
        const long long gr0 = row0 + mBase + qrow;
        const long long gr1 = gr0 + 8;
        const int nc = qk * 2;
        const bool w0 = gr0 < (long long)M;
        const bool w1 = gr1 < (long long)M;
#pragma unroll
        for (int nt = 0; nt < 16; nt++) {
            const int c0 = nt * 8 + nc;
            float bz0 = 0.f, bz1 = 0.f;
            if (bias) { bz0 = __ldg(bias + c0); bz1 = __ldg(bias + c0 + 1); }
            if (w0) {
                __half2 h = __floats2half2_rn(acc[nt][0] + bz0, acc[nt][1] + bz1);
                *(__half2*)(C + gr0 * H + c0) = h;
            }
            if (w1) {
                __half2 h = __floats2half2_rn(acc[nt][2] + bz0, acc[nt][3] + bz1);
                *(__half2*)(C + gr1 * H + c0) = h;
            }
        }
    }
}

// ---- edge pass ----------------------------------------------------------
// out[e] = b2 + sum_j relu(U[row[e]][j] + V[col[e]][j]) * W2[j]   (b1 in V)
// R9 layout: one warp per 4 edges/iter, lane covers channels 4*lane..4*lane+3
// (uint2 = 4 halves) -> each gather is one warp-wide coalesced 256B row read.
// half2 add+relu, fp32 dot; 11-shuffle two-stage reduction.
__global__ void __launch_bounds__(256) edge_k(const __half* __restrict__ U,
                                              const __half* __restrict__ V,
                                              const void* __restrict__ rowp,
                                              const void* __restrict__ colp,
                                              const float* __restrict__ W2,
                                              const float* __restrict__ b2,
                                              float* __restrict__ out,
                                              int E) {
    const int lane = threadIdx.x & 31;
    const int w  = (blockIdx.x * blockDim.x + threadIdx.x) >> 5;
    const int nW = (gridDim.x * blockDim.x) >> 5;

    const bool idx64 = (g_idx64 != 0);
    const int*       r32 = (const int*)rowp;
    const int*       c32 = (const int*)colp;
    const long long* r64 = (const long long*)rowp;
    const long long* c64 = (const long long*)colp;

    const float4 w2v = ((const float4*)W2)[lane];
    const float bias2 = b2[0];
    const __half2 zero = __float2half2_rn(0.f);

    for (int e = 4 * w; e < E; e += 4 * nW) {
        long long ri[4], ci[4];
#pragma unroll
        for (int j = 0; j < 4; j++) {
            int ej = e + j;
            if (ej >= E) ej = E - 1;
            if (idx64) { ri[j] = r64[ej]; ci[j] = c64[ej]; }
            else       { ri[j] = (long long)r32[ej]; ci[j] = (long long)c32[ej]; }
        }
        uint2 u[4], v[4];
#pragma unroll
        for (int j = 0; j < 4; j++) {
            u[j] = ((const uint2*)(U + ri[j] * (long long)H))[lane];
            v[j] = ((const uint2*)(V + ci[j] * (long long)H))[lane];
        }
        float s0, s1, s2, s3;
        {
            float sj[4];
#pragma unroll
            for (int j = 0; j < 4; j++) {
                __half2 a0 = __hmax2(__hadd2(*(__half2*)&u[j].x, *(__half2*)&v[j].x), zero);
                __half2 a1 = __hmax2(__hadd2(*(__half2*)&u[j].y, *(__half2*)&v[j].y), zero);
                float2 f0 = __half22float2(a0);
                float2 f1 = __half22float2(a1);
                float t = f0.x * w2v.x;
                t = fmaf(f0.y, w2v.y, t);
                t = fmaf(f1.x, w2v.z, t);
                sj[j] = fmaf(f1.y, w2v.w, t);
            }
            s0 = sj[0]; s1 = sj[1]; s2 = sj[2]; s3 = sj[3];
        }
        // Stage 1: sum within 4-lane groups (all four edge sums).
        s0 += __shfl_xor_sync(0xffffffffu, s0, 1);
        s1 += __shfl_xor_sync(0xffffffffu, s1, 1);
        s2 += __shfl_xor_sync(0xffffffffu, s2, 1);
        s3 += __shfl_xor_sync(0xffffffffu, s3, 1);
        s0 += __shfl_xor_sync(0xffffffffu, s0, 2);
        s1 += __shfl_xor_sync(0xffffffffu, s1, 2);
        s2 += __shfl_xor_sync(0xffffffffu, s2, 2);
        s3 += __shfl_xor_sync(0xffffffffu, s3, 2);
        // Stage 2: lane picks edge (lane&3), reduce across the 8 groups.
        const int j = lane & 3;
        float t = (j == 0) ? s0 : (j == 1) ? s1 : (j == 2) ? s2 : s3;
        t += __shfl_xor_sync(0xffffffffu, t, 4);
        t += __shfl_xor_sync(0xffffffffu, t, 8);
        t += __shfl_xor_sync(0xffffffffu, t, 16);

        if (lane < 4 && e + lane < E) out[e + lane] = t + bias2;
    }
}

extern "C" void kernel_launch(void* const* d_in, const int* in_sizes, int n_in,
                              void* d_out, int out_size) {
    const float* zc  = (const float*)d_in[0];
    const float* za  = (const float*)d_in[1];
    const void*  row = d_in[2];
    const void*  col = d_in[3];
    const float* W1  = (const float*)d_in[4];
    const float* b1  = (const float*)d_in[5];
    const float* W2  = (const float*)d_in[6];
    const float* b2  = (const float*)d_in[7];
    float* out = (float*)d_out;

    const int Mc = in_sizes[0] / H;
    const int Ma = in_sizes[1] / H;
    const int E  = in_sizes[2];
    const int nTc = (Mc + 127) / 128;
    const int nTa = (Ma + 127) / 128;

    __half* U = nullptr;
    __half* V = nullptr;
    cudaGetSymbolAddress((void**)&U, g_U);
    cudaGetSymbolAddress((void**)&V, g_V);

    int nSM = 148;
    cudaDeviceGetAttribute(&nSM, cudaDevAttrMultiProcessorCount, 0);

    probe_idx_dtype<<<1, 1>>>((const int*)row, E);
    gemm_tc<<<nSM, 256>>>(zc, W1, U, nullptr, Mc, nTc);
    gemm_tc<<<nSM, 256>>>(za, W1 + H * H, V, b1, Ma, nTa);
    edge_k<<<4096, 256>>>(U, V, row, col, W2, b2, out, E);
}

// round 13
// speedup vs baseline: 1.1337x; 1.0254x over previous
#include <cuda_runtime.h>
#include <cuda_fp16.h>
#include <cstdint>
#include <cstddef>

#define H 128
#define NCUST_MAX 1000000
#define NART_MAX  100000

// U = Zc @ W1c, V = Za @ W1a + b1, stored fp16
__device__ __half g_U[(size_t)NCUST_MAX * H];
__device__ __half g_V[(size_t)NART_MAX * H];
__device__ int    g_idx64;   // 1 if row/col are int64, 0 if int32

__device__ __forceinline__ void mma_f16(float c[4],
                                        uint32_t a0, uint32_t a1, uint32_t a2, uint32_t a3,
                                        uint32_t b0, uint32_t b1) {
    asm volatile(
        "mma.sync.aligned.m16n8k16.row.col.f32.f16.f16.f32 "
        "{%0,%1,%2,%3}, {%4,%5,%6,%7}, {%8,%9}, {%0,%1,%2,%3};"
        : "+f"(c[0]), "+f"(c[1]), "+f"(c[2]), "+f"(c[3])
        : "r"(a0), "r"(a1), "r"(a2), "r"(a3), "r"(b0), "r"(b1));
}

__device__ __forceinline__ uint32_t pack_h2(float lo, float hi) {
    __half2 h = __floats2half2_rn(lo, hi);
    return *(uint32_t*)&h;
}

// ---- fused persistent fp16 GEMM (U tiles then V tiles) -------------------
// 256 threads (8 warps), M-tile 128, persistent grid = #SMs.
// K-permutation pi (same on A and B, cancels in the contraction):
//   canonical k (kt, 2q+d)   <- mem col kt*16 + 4q + d
//   canonical k (kt, 2q+8+d) <- mem col kt*16 + 4q + 2 + d
//   -> each lane's A elements per kt are one contiguous float4 (LDG.128).
// N-permutation sigma (folded into pack AND epilogue, cancels):
//   canonical (nt, n) -> mem col (nt>>2)*32 + (n>>1)*8 + (nt&3)*2 + (n&1)
//   -> each lane's epilogue output is 16B contiguous (STG.128).
__global__ void __launch_bounds__(256) gemm_fused(
    const float* __restrict__ Azc, const float* __restrict__ Aza,
    const float* __restrict__ W1,
    __half* __restrict__ U, __half* __restrict__ V,
    const float* __restrict__ b1,
    int Mc, int Ma, int nTc, int nTa,
    const int* __restrict__ probeIdx, int probeE) {
    extern __shared__ uint2 Bf[];   // 2 halves x 8kt x 16nt x 32 lanes = 8192 uint2 (64KB)

    const int tid  = threadIdx.x;
    const int wid  = tid >> 5;
    const int lane = tid & 31;
    const int qrow = lane >> 2;   // 0..7
    const int qk   = lane & 3;    // 0..3
    const int mBase = wid * 16;
    const int nTiles = nTc + nTa;

    // Probe index dtype (block 0; edge_k launches after this kernel).
    if (blockIdx.x == 0 && tid == 0) {
        int all_zero = 1;
#pragma unroll
        for (int i = 0; i < 16; i++) {
            int pos = 2 * i + 1;
            if (pos < 2 * probeE && probeIdx[pos] != 0) all_zero = 0;
        }
        g_idx64 = all_zero;
    }

    // One-time: pack both W1 halves into permuted m16n8k16 fragments.
    for (int idx = tid; idx < 8192; idx += 256) {
        int h   = idx >> 12;          // 0 = U half, 1 = V half
        int rem = idx & 4095;
        int kt  = rem >> 9;
        int nt  = (rem >> 5) & 15;
        int l   = rem & 31;
        int q   = l & 3;
        int u   = l >> 2;
        int n_mem = (nt >> 2) * 32 + (u >> 1) * 8 + (nt & 3) * 2 + (u & 1);  // sigma
        int k0 = kt * 16 + q * 4;                                            // pi
        const float* Bh = W1 + (size_t)h * H * H;
        uint2 v;
        v.x = pack_h2(Bh[(k0 + 0) * H + n_mem], Bh[(k0 + 1) * H + n_mem]);
        v.y = pack_h2(Bh[(k0 + 2) * H + n_mem], Bh[(k0 + 3) * H + n_mem]);
        Bf[idx] = v;
    }
    __syncthreads();

    const long long s = gridDim.x;

    // Raw A fragments: per kt one float4 per row (permuted-k contiguous).
    float4 r0[8], r1[8];

    auto loadRaw = [&](long long t) {
        if (t >= (long long)nTiles) return;
        const bool isV = t >= (long long)nTc;
        const float* A = isV ? Aza : Azc;
        const int   M  = isV ? Ma : Mc;
        const long long trow = isV ? t - nTc : t;
        long long g0 = trow * 128 + mBase + qrow;
        long long g1 = g0 + 8;
        if (g0 >= (long long)M) g0 = (long long)M - 1;  // clamp; store guarded
        if (g1 >= (long long)M) g1 = (long long)M - 1;
        const float* p0 = A + g0 * (long long)H + qk * 4;
        const float* p1 = A + g1 * (long long)H + qk * 4;
#pragma unroll
        for (int kt = 0; kt < 8; kt++) {
            r0[kt] = *(const float4*)(p0 + kt * 16);
            r1[kt] = *(const float4*)(p1 + kt * 16);
        }
    };

    long long t = blockIdx.x;
    loadRaw(t);

    for (; t < (long long)nTiles; t += s) {
        const bool isV = t >= (long long)nTc;
        const int   M  = isV ? Ma : Mc;
        __half* C      = isV ? V : U;
        const float* bias = isV ? b1 : nullptr;
        const long long trow = isV ? t - nTc : t;
        const uint2* bfH = Bf + (isV ? 4096 : 0);

        // Convert raw -> packed fragments (frees raw for prefetch).
        uint32_t pa0[8], pa1[8], pa2[8], pa3[8];
#pragma unroll
        for (int kt = 0; kt < 8; kt++) {
            pa0[kt] = pack_h2(r0[kt].x, r0[kt].y);
            pa2[kt] = pack_h2(r0[kt].z, r0[kt].w);
            pa1[kt] = pack_h2(r1[kt].x, r1[kt].y);
            pa3[kt] = pack_h2(r1[kt].z, r1[kt].w);
        }
        loadRaw(t + s);   // prefetch next tile during MMAs

        float acc[16][4];
#pragma unroll
        for (int nt = 0; nt < 16; nt++) {
            acc[nt][0] = 0.f; acc[nt][1] = 0.f; acc[nt][2] = 0.f; acc[nt][3] = 0.f;
        }

#pragma unroll
        for (int kt = 0; kt < 8; kt++) {
            const uint2* bf = bfH + (kt * 16) * 32 + lane;
#pragma unroll
            for (int nt = 0; nt < 16; nt++) {
                uint2 bv = bf[nt * 32];
                mma_f16(acc[nt], pa0[kt], pa1[kt], pa2[kt], pa3[kt], bv.x, bv.y);
            }
        }

        // Epilogue: STG.128 per group of 4 nt (n-permuted contiguous).
        const long long gr0 = trow * 128 + mBase + qrow;
        const long long gr1 = gr0 + 8;
        const bool w0 = gr0 < (long long)M;
        const bool w1 = gr1 < (long long)M;
#pragma unroll
        for (int g = 0; g < 4; g++) {
            const int m0 = g * 32 + qk * 8;
            float4 bz0 = make_float4(0.f, 0.f, 0.f, 0.f);
            float4 bz1 = make_float4(0.f, 0.f, 0.f, 0.f);
            if (bias) {
                bz0 = *(const float4*)(bias + m0);
                bz1 = *(const float4*)(bias + m0 + 4);
            }
            if (w0) {
                uint4 o;
                o.x = pack_h2(acc[4*g+0][0] + bz0.x, acc[4*g+0][1] + bz0.y);
                o.y = pack_h2(acc[4*g+1][0] + bz0.z, acc[4*g+1][1] + bz0.w);
                o.z = pack_h2(acc[4*g+2][0] + bz1.x, acc[4*g+2][1] + bz1.y);
                o.w = pack_h2(acc[4*g+3][0] + bz1.z, acc[4*g+3][1] + bz1.w);
                *(uint4*)(C + gr0 * H + m0) = o;
            }
            if (w1) {
                uint4 o;
                o.x = pack_h2(acc[4*g+0][2] + bz0.x, acc[4*g+0][3] + bz0.y);
                o.y = pack_h2(acc[4*g+1][2] + bz0.z, acc[4*g+1][3] + bz0.w);
                o.z = pack_h2(acc[4*g+2][2] + bz1.x, acc[4*g+2][3] + bz1.y);
                o.w = pack_h2(acc[4*g+3][2] + bz1.z, acc[4*g+3][3] + bz1.w);
                *(uint4*)(C + gr1 * H + m0) = o;
            }
        }
    }
}

// ---- edge pass ----------------------------------------------------------
// out[e] = b2 + sum_j relu(U[row[e]][j] + V[col[e]][j]) * W2[j]   (b1 in V)
// One warp per 8 edges/iter: 16 independent 256B row gathers in flight.
// Reduction (FIXED): stage 1 sums within 8-lane groups (xor 1,2,4) -> 4
// group-partials per edge; stage 2 selects j = lane&7 (bits 0-2) and reduces
// over xor 8,16 (bits 3-4, disjoint from the select bits; the 4 lanes
// {L, L^8, L^16, L^24} cover all 4 groups).
__global__ void __launch_bounds__(256) edge_k(const __half* __restrict__ U,
                                              const __half* __restrict__ V,
                                              const void* __restrict__ rowp,
                                              const void* __restrict__ colp,
                                              const float* __restrict__ W2,
                                              const float* __restrict__ b2,
                                              float* __restrict__ out,
                                              int E) {
    const int lane = threadIdx.x & 31;
    const int w  = (blockIdx.x * blockDim.x + threadIdx.x) >> 5;
    const int nW = (gridDim.x * blockDim.x) >> 5;

    const bool idx64 = (g_idx64 != 0);
    const int*       r32 = (const int*)rowp;
    const int*       c32 = (const int*)colp;
    const long long* r64 = (const long long*)rowp;
    const long long* c64 = (const long long*)colp;

    const float4 w2v = ((const float4*)W2)[lane];
    const float bias2 = b2[0];
    const __half2 zero = __float2half2_rn(0.f);

    for (int e = 8 * w; e < E; e += 8 * nW) {
        long long ri[8], ci[8];
#pragma unroll
        for (int j = 0; j < 8; j++) {
            int ej = e + j;
            if (ej >= E) ej = E - 1;
            if (idx64) { ri[j] = r64[ej]; ci[j] = c64[ej]; }
            else       { ri[j] = (long long)r32[ej]; ci[j] = (long long)c32[ej]; }
        }
        uint2 u[8], v[8];
#pragma unroll
        for (int j = 0; j < 8; j++) {
            u[j] = ((const uint2*)(U + ri[j] * (long long)H))[lane];
            v[j] = ((const uint2*)(V + ci[j] * (long long)H))[lane];
        }
        float sj[8];
#pragma unroll
        for (int j = 0; j < 8; j++) {
            __half2 a0 = __hmax2(__hadd2(*(__half2*)&u[j].x, *(__half2*)&v[j].x), zero);
            __half2 a1 = __hmax2(__hadd2(*(__half2*)&u[j].y, *(__half2*)&v[j].y), zero);
            float2 f0 = __half22float2(a0);
            float2 f1 = __half22float2(a1);
            float t = f0.x * w2v.x;
            t = fmaf(f0.y, w2v.y, t);
            t = fmaf(f1.x, w2v.z, t);
            sj[j] = fmaf(f1.y, w2v.w, t);
        }
        // Stage 1: sum within 8-lane groups (bits 0-2).
#pragma unroll
        for (int j = 0; j < 8; j++) {
            sj[j] += __shfl_xor_sync(0xffffffffu, sj[j], 1);
            sj[j] += __shfl_xor_sync(0xffffffffu, sj[j], 2);
            sj[j] += __shfl_xor_sync(0xffffffffu, sj[j], 4);
        }
        // Stage 2: lane picks edge j = lane&7; reduce over bits 3-4.
        const int j = lane & 7;
        float t = sj[0];
        if (j == 1) t = sj[1];
        if (j == 2) t = sj[2];
        if (j == 3) t = sj[3];
        if (j == 4) t = sj[4];
        if (j == 5) t = sj[5];
        if (j == 6) t = sj[6];
        if (j == 7) t = sj[7];
        t += __shfl_xor_sync(0xffffffffu, t, 8);
        t += __shfl_xor_sync(0xffffffffu, t, 16);

        if (lane < 8 && e + lane < E) out[e + lane] = t + bias2;
    }
}

extern "C" void kernel_launch(void* const* d_in, const int* in_sizes, int n_in,
                              void* d_out, int out_size) {
    const float* zc  = (const float*)d_in[0];
    const float* za  = (const float*)d_in[1];
    const void*  row = d_in[2];
    const void*  col = d_in[3];
    const float* W1  = (const float*)d_in[4];
    const float* b1  = (const float*)d_in[5];
    const float* W2  = (const float*)d_in[6];
    const float* b2  = (const float*)d_in[7];
    float* out = (float*)d_out;

    const int Mc = in_sizes[0] / H;
    const int Ma = in_sizes[1] / H;
    const int E  = in_sizes[2];
    const int nTc = (Mc + 127) / 128;
    const int nTa = (Ma + 127) / 128;

    __half* U = nullptr;
    __half* V = nullptr;
    cudaGetSymbolAddress((void**)&U, g_U);
    cudaGetSymbolAddress((void**)&V, g_V);

    int nSM = 148;
    cudaDeviceGetAttribute(&nSM, cudaDevAttrMultiProcessorCount, 0);

    const int smem = 8192 * sizeof(uint2);   // 64KB
    cudaFuncSetAttribute(gemm_fused, cudaFuncAttributeMaxDynamicSharedMemorySize, smem);

    gemm_fused<<<nSM, 256, smem>>>(zc, za, W1, U, V, b1,
                                   Mc, Ma, nTc, nTa, (const int*)row, E);
    edge_k<<<4096, 256>>>(U, V, row, col, W2, b2, out, E);
}

// round 17
// speedup vs baseline: 1.5664x; 1.3816x over previous
#include <cuda_runtime.h>
#include <cuda_fp16.h>
#include <cstdint>
#include <cstddef>

#define H 128
#define NCUST_MAX 1000000
#define NART_MAX  100000

// U = Zc @ W1c, V = Za @ W1a + b1, stored fp16
__device__ __half g_U[(size_t)NCUST_MAX * H];
__device__ __half g_V[(size_t)NART_MAX * H];
__device__ int    g_idx64;   // 1 if row/col are int64, 0 if int32

__device__ __forceinline__ void mma_f16(float c[4],
                                        uint32_t a0, uint32_t a1, uint32_t a2, uint32_t a3,
                                        uint32_t b0, uint32_t b1) {
    asm volatile(
        "mma.sync.aligned.m16n8k16.row.col.f32.f16.f16.f32 "
        "{%0,%1,%2,%3}, {%4,%5,%6,%7}, {%8,%9}, {%0,%1,%2,%3};"
        : "+f"(c[0]), "+f"(c[1]), "+f"(c[2]), "+f"(c[3])
        : "r"(a0), "r"(a1), "r"(a2), "r"(a3), "r"(b0), "r"(b1));
}

__device__ __forceinline__ uint32_t pack_h2(float lo, float hi) {
    __half2 h = __floats2half2_rn(lo, hi);
    return *(uint32_t*)&h;
}

// ---- fused persistent fp16 GEMM (U tiles then V tiles) -------------------
// (bit-identical to R13's measured ~213us version)
// K-permutation pi (same on A and B, cancels in the contraction):
//   -> each lane's A elements per kt are one contiguous float4 (LDG.128).
// N-permutation sigma (folded into pack AND epilogue, cancels):
//   -> each lane's epilogue output is 16B contiguous (STG.128).
__global__ void __launch_bounds__(256) gemm_fused(
    const float* __restrict__ Azc, const float* __restrict__ Aza,
    const float* __restrict__ W1,
    __half* __restrict__ U, __half* __restrict__ V,
    const float* __restrict__ b1,
    int Mc, int Ma, int nTc, int nTa,
    const int* __restrict__ probeIdx, int probeE) {
    extern __shared__ uint2 Bf[];   // 2 halves x 8kt x 16nt x 32 lanes (64KB)

    const int tid  = threadIdx.x;
    const int wid  = tid >> 5;
    const int lane = tid & 31;
    const int qrow = lane >> 2;
    const int qk   = lane & 3;
    const int mBase = wid * 16;
    const int nTiles = nTc + nTa;

    if (blockIdx.x == 0 && tid == 0) {
        int all_zero = 1;
#pragma unroll
        for (int i = 0; i < 16; i++) {
            int pos = 2 * i + 1;
            if (pos < 2 * probeE && probeIdx[pos] != 0) all_zero = 0;
        }
        g_idx64 = all_zero;
    }

    for (int idx = tid; idx < 8192; idx += 256) {
        int h   = idx >> 12;
        int rem = idx & 4095;
        int kt  = rem >> 9;
        int nt  = (rem >> 5) & 15;
        int l   = rem & 31;
        int q   = l & 3;
        int u   = l >> 2;
        int n_mem = (nt >> 2) * 32 + (u >> 1) * 8 + (nt & 3) * 2 + (u & 1);  // sigma
        int k0 = kt * 16 + q * 4;                                            // pi
        const float* Bh = W1 + (size_t)h * H * H;
        uint2 v;
        v.x = pack_h2(Bh[(k0 + 0) * H + n_mem], Bh[(k0 + 1) * H + n_mem]);
        v.y = pack_h2(Bh[(k0 + 2) * H + n_mem], Bh[(k0 + 3) * H + n_mem]);
        Bf[idx] = v;
    }
    __syncthreads();

    const long long s = gridDim.x;
    float4 r0[8], r1[8];

    auto loadRaw = [&](long long t) {
        if (t >= (long long)nTiles) return;
        const bool isV = t >= (long long)nTc;
        const float* A = isV ? Aza : Azc;
        const int   M  = isV ? Ma : Mc;
        const long long trow = isV ? t - nTc : t;
        long long g0 = trow * 128 + mBase + qrow;
        long long g1 = g0 + 8;
        if (g0 >= (long long)M) g0 = (long long)M - 1;
        if (g1 >= (long long)M) g1 = (long long)M - 1;
        const float* p0 = A + g0 * (long long)H + qk * 4;
        const float* p1 = A + g1 * (long long)H + qk * 4;
#pragma unroll
        for (int kt = 0; kt < 8; kt++) {
            r0[kt] = *(const float4*)(p0 + kt * 16);
            r1[kt] = *(const float4*)(p1 + kt * 16);
        }
    };

    long long t = blockIdx.x;
    loadRaw(t);

    for (; t < (long long)nTiles; t += s) {
        const bool isV = t >= (long long)nTc;
        const int   M  = isV ? Ma : Mc;
        __half* C      = isV ? V : U;
        const float* bias = isV ? b1 : nullptr;
        const long long trow = isV ? t - nTc : t;
        const uint2* bfH = Bf + (isV ? 4096 : 0);

        uint32_t pa0[8], pa1[8], pa2[8], pa3[8];
#pragma unroll
        for (int kt = 0; kt < 8; kt++) {
            pa0[kt] = pack_h2(r0[kt].x, r0[kt].y);
            pa2[kt] = pack_h2(r0[kt].z, r0[kt].w);
            pa1[kt] = pack_h2(r1[kt].x, r1[kt].y);
            pa3[kt] = pack_h2(r1[kt].z, r1[kt].w);
        }
        loadRaw(t + s);

        float acc[16][4];
#pragma unroll
        for (int nt = 0; nt < 16; nt++) {
            acc[nt][0] = 0.f; acc[nt][1] = 0.f; acc[nt][2] = 0.f; acc[nt][3] = 0.f;
        }

#pragma unroll
        for (int kt = 0; kt < 8; kt++) {
            const uint2* bf = bfH + (kt * 16) * 32 + lane;
#pragma unroll
            for (int nt = 0; nt < 16; nt++) {
                uint2 bv = bf[nt * 32];
                mma_f16(acc[nt], pa0[kt], pa1[kt], pa2[kt], pa3[kt], bv.x, bv.y);
            }
        }

        const long long gr0 = trow * 128 + mBase + qrow;
        const long long gr1 = gr0 + 8;
        const bool w0 = gr0 < (long long)M;
        const bool w1 = gr1 < (long long)M;
#pragma unroll
        for (int g = 0; g < 4; g++) {
            const int m0 = g * 32 + qk * 8;
            float4 bz0 = make_float4(0.f, 0.f, 0.f, 0.f);
            float4 bz1 = make_float4(0.f, 0.f, 0.f, 0.f);
            if (bias) {
                bz0 = *(const float4*)(bias + m0);
                bz1 = *(const float4*)(bias + m0 + 4);
            }
            if (w0) {
                uint4 o;
                o.x = pack_h2(acc[4*g+0][0] + bz0.x, acc[4*g+0][1] + bz0.y);
                o.y = pack_h2(acc[4*g+1][0] + bz0.z, acc[4*g+1][1] + bz0.w);
                o.z = pack_h2(acc[4*g+2][0] + bz1.x, acc[4*g+2][1] + bz1.y);
                o.w = pack_h2(acc[4*g+3][0] + bz1.z, acc[4*g+3][1] + bz1.w);
                *(uint4*)(C + gr0 * H + m0) = o;
            }
            if (w1) {
                uint4 o;
                o.x = pack_h2(acc[4*g+0][2] + bz0.x, acc[4*g+0][3] + bz0.y);
                o.y = pack_h2(acc[4*g+1][2] + bz0.z, acc[4*g+1][3] + bz0.w);
                o.z = pack_h2(acc[4*g+2][2] + bz1.x, acc[4*g+2][3] + bz1.y);
                o.w = pack_h2(acc[4*g+3][2] + bz1.z, acc[4*g+3][3] + bz1.w);
                *(uint4*)(C + gr1 * H + m0) = o;
            }
        }
    }
}

// ---- edge pass (R11 4-edge layout + cache-policy split) ------------------
// out[e] = b2 + sum_j relu(U[row[e]][j] + V[col[e]][j]) * W2[j]   (b1 in V)
// One warp per 4 edges/iter; lane covers channels 4*lane..4*lane+3.
// U gathers: __ldcs (streaming, no L1 allocate - 256MB array, ~no reuse).
// V gathers: __ldg  (25.6MB, L2-resident, high reuse - keep cacheable).
__global__ void __launch_bounds__(256) edge_k(const __half* __restrict__ U,
                                              const __half* __restrict__ V,
                                              const void* __restrict__ rowp,
                                              const void* __restrict__ colp,
                                              const float* __restrict__ W2,
                                              const float* __restrict__ b2,
                                              float* __restrict__ out,
                                              int E) {
    const int lane = threadIdx.x & 31;
    const int w  = (blockIdx.x * blockDim.x + threadIdx.x) >> 5;
    const int nW = (gridDim.x * blockDim.x) >> 5;

    const bool idx64 = (g_idx64 != 0);
    const int*       r32 = (const int*)rowp;
    const int*       c32 = (const int*)colp;
    const long long* r64 = (const long long*)rowp;
    const long long* c64 = (const long long*)colp;

    const float4 w2v = ((const float4*)W2)[lane];
    const float bias2 = b2[0];
    const __half2 zero = __float2half2_rn(0.f);

    for (int e = 4 * w; e < E; e += 4 * nW) {
        long long ri[4], ci[4];
        if (!idx64 && e + 3 < E) {
            // Vectorized int32 index fetch: one LDG.128 per array for 4 edges.
            int4 rv = *(const int4*)(r32 + e);
            int4 cv = *(const int4*)(c32 + e);
            ri[0] = rv.x; ri[1] = rv.y; ri[2] = rv.z; ri[3] = rv.w;
            ci[0] = cv.x; ci[1] = cv.y; ci[2] = cv.z; ci[3] = cv.w;
        } else {
#pragma unroll
            for (int j = 0; j < 4; j++) {
                int ej = e + j;
                if (ej >= E) ej = E - 1;
                if (idx64) { ri[j] = r64[ej]; ci[j] = c64[ej]; }
                else       { ri[j] = (long long)r32[ej]; ci[j] = (long long)c32[ej]; }
            }
        }
        uint2 u[4], v[4];
#pragma unroll
        for (int j = 0; j < 4; j++) {
            u[j] = __ldcs(((const uint2*)(U + ri[j] * (long long)H)) + lane);
            v[j] = __ldg (((const uint2*)(V + ci[j] * (long long)H)) + lane);
        }
        float s0, s1, s2, s3;
        {
            float sj[4];
#pragma unroll
            for (int j = 0; j < 4; j++) {
                __half2 a0 = __hmax2(__hadd2(*(__half2*)&u[j].x, *(__half2*)&v[j].x), zero);
                __half2 a1 = __hmax2(__hadd2(*(__half2*)&u[j].y, *(__half2*)&v[j].y), zero);
                float2 f0 = __half22float2(a0);
                float2 f1 = __half22float2(a1);
                float t = f0.x * w2v.x;
                t = fmaf(f0.y, w2v.y, t);
                t = fmaf(f1.x, w2v.z, t);
                sj[j] = fmaf(f1.y, w2v.w, t);
            }
            s0 = sj[0]; s1 = sj[1]; s2 = sj[2]; s3 = sj[3];
        }
        // Stage 1: sum within 4-lane groups (bits 0-1).
        s0 += __shfl_xor_sync(0xffffffffu, s0, 1);
        s1 += __shfl_xor_sync(0xffffffffu, s1, 1);
        s2 += __shfl_xor_sync(0xffffffffu, s2, 1);
        s3 += __shfl_xor_sync(0xffffffffu, s3, 1);
        s0 += __shfl_xor_sync(0xffffffffu, s0, 2);
        s1 += __shfl_xor_sync(0xffffffffu, s1, 2);
        s2 += __shfl_xor_sync(0xffffffffu, s2, 2);
        s3 += __shfl_xor_sync(0xffffffffu, s3, 2);
        // Stage 2: lane picks edge (lane&3, bits 0-1); reduce bits 2-4.
        const int j = lane & 3;
        float t = (j == 0) ? s0 : (j == 1) ? s1 : (j == 2) ? s2 : s3;
        t += __shfl_xor_sync(0xffffffffu, t, 4);
        t += __shfl_xor_sync(0xffffffffu, t, 8);
        t += __shfl_xor_sync(0xffffffffu, t, 16);

        if (lane < 4 && e + lane < E) out[e + lane] = t + bias2;
    }
}

extern "C" void kernel_launch(void* const* d_in, const int* in_sizes, int n_in,
                              void* d_out, int out_size) {
    const float* zc  = (const float*)d_in[0];
    const float* za  = (const float*)d_in[1];
    const void*  row = d_in[2];
    const void*  col = d_in[3];
    const float* W1  = (const float*)d_in[4];
    const float* b1  = (const float*)d_in[5];
    const float* W2  = (const float*)d_in[6];
    const float* b2  = (const float*)d_in[7];
    float* out = (float*)d_out;

    const int Mc = in_sizes[0] / H;
    const int Ma = in_sizes[1] / H;
    const int E  = in_sizes[2];
    const int nTc = (Mc + 127) / 128;
    const int nTa = (Ma + 127) / 128;

    __half* U = nullptr;
    __half* V = nullptr;
    cudaGetSymbolAddress((void**)&U, g_U);
    cudaGetSymbolAddress((void**)&V, g_V);

    int nSM = 148;
    cudaDeviceGetAttribute(&nSM, cudaDevAttrMultiProcessorCount, 0);

    const int smem = 8192 * sizeof(uint2);   // 64KB
    cudaFuncSetAttribute(gemm_fused, cudaFuncAttributeMaxDynamicSharedMemorySize, smem);

    gemm_fused<<<nSM, 256, smem>>>(zc, za, W1, U, V, b1,
                                   Mc, Ma, nTc, nTa, (const int*)row, E);
    edge_k<<<4096, 256>>>(U, V, row, col, W2, b2, out, E);
}